// round 9
// baseline (speedup 1.0000x reference)
#include <cuda_runtime.h>
#include <cuda_bf16.h>
#include <cuda_fp16.h>
#include <cstdint>

#define NN 100000
#define EE 1600000
#define HD 128
#define NC 8
#define EPS_BN 1e-5f
#define SLOPE 0.01f

#define SCAN_BLK 1024
#define SCAN_GRID ((NN + SCAN_BLK - 1) / SCAN_BLK)   // 98
#define GEMM_GRID ((NN + 127) / 128)                 // 782

// padded smem row stride (bf16 elems)
#define LDA 136
#define OFF_A_HI 0
#define OFF_A_LO (128 * LDA * 2)            // 34816
#define OFF_W_HI (2 * 128 * LDA * 2)        // 69632
#define OFF_W_LO (3 * 128 * LDA * 2)        // 104448
#define OFF_STATS (4 * 128 * LDA * 2)       // 139264
#define SM_TOTAL (OFF_STATS + 256 * 4)      // 140288

// ---- device scratch (allocation-free) ----
__device__ float  g_A[(size_t)NN * HD];      // agg output (fp32)
__device__ __half g_Xh[(size_t)NN * HD];     // fp16 node_feat
__device__ __half g_Bh[(size_t)NN * HD];     // fp16 activations
__device__ float g_outnorm[NN];
__device__ float g_innorm[NN];
__device__ int   g_srccnt[NN];
__device__ int   g_dstcnt[NN];
__device__ int   g_excl[NN];
__device__ int   g_blksum[SCAN_GRID];
__device__ int   g_rowptr[NN + 1];
__device__ int   g_cursor[NN];
__device__ int2  g_epk[EE];                  // packed {src, bits(outnorm[src])}
__device__ float g_stats[2 * HD];
__device__ float g_scale[HD];
__device__ float g_bias[HD];
__device__ __nv_bfloat16 g_Wtb[8 * 16384];

// ============================ CSR build =====================================
__global__ void zero_cnt_kernel(int* a, int* b) {
    int i = blockIdx.x * blockDim.x + threadIdx.x;
    if (i < NN) { a[i] = 0; b[i] = 0; }
}
__global__ void zero_stats_kernel(float* stats) {
    int i = threadIdx.x;
    if (i < 2 * HD) stats[i] = 0.f;
}
__global__ void hist_kernel(const int* __restrict__ src, const int* __restrict__ dst,
                            int* srccnt, int* dstcnt) {
    int e = blockIdx.x * blockDim.x + threadIdx.x;
    if (e >= EE) return;
    atomicAdd(&srccnt[src[e]], 1);
    atomicAdd(&dstcnt[dst[e]], 1);
}
__global__ void norm_kernel(const int* __restrict__ srccnt, const int* __restrict__ dstcnt,
                            float* outnorm, float* innorm) {
    int i = blockIdx.x * blockDim.x + threadIdx.x;
    if (i >= NN) return;
    outnorm[i] = rsqrtf(fmaxf((float)srccnt[i], 1.f));
    innorm[i]  = rsqrtf(fmaxf((float)dstcnt[i], 1.f));
}
__global__ void scan1_kernel(const int* __restrict__ cnt, int* excl, int* blksum) {
    __shared__ int sh[SCAN_BLK];
    int i = blockIdx.x * SCAN_BLK + threadIdx.x;
    int v = (i < NN) ? cnt[i] : 0;
    sh[threadIdx.x] = v;
    __syncthreads();
    for (int off = 1; off < SCAN_BLK; off <<= 1) {
        int t = (threadIdx.x >= off) ? sh[threadIdx.x - off] : 0;
        __syncthreads();
        sh[threadIdx.x] += t;
        __syncthreads();
    }
    if (i < NN) excl[i] = sh[threadIdx.x] - v;
    if (threadIdx.x == SCAN_BLK - 1) blksum[blockIdx.x] = sh[threadIdx.x];
}
__global__ void scan2_kernel(int* blksum) {
    __shared__ int sh[1024];
    int i = threadIdx.x;
    int v = (i < SCAN_GRID) ? blksum[i] : 0;
    sh[i] = v;
    __syncthreads();
    for (int off = 1; off < 1024; off <<= 1) {
        int t = (i >= off) ? sh[i - off] : 0;
        __syncthreads();
        sh[i] += t;
        __syncthreads();
    }
    if (i < SCAN_GRID) blksum[i] = sh[i] - v;
}
__global__ void scan3_kernel(const int* __restrict__ excl, const int* __restrict__ blksum,
                             int* rowptr, int* cursor) {
    int i = blockIdx.x * SCAN_BLK + threadIdx.x;
    if (i < NN) {
        int r = excl[i] + blksum[blockIdx.x];
        rowptr[i] = r;
        cursor[i] = r;
    }
    if (i == 0) rowptr[NN] = EE;
}
// fill packed edge list: {src, outnorm[src]}
__global__ void fill_kernel(const int* __restrict__ src, const int* __restrict__ dst,
                            const float* __restrict__ outnorm,
                            int* cursor, int2* epk) {
    int e = blockIdx.x * blockDim.x + threadIdx.x;
    if (e >= EE) return;
    int s = src[e];
    float w = outnorm[s];
    int p = atomicAdd(&cursor[dst[e]], 1);
    epk[p] = make_int2(s, __float_as_int(w));
}

// node_feat fp32 -> fp16
__global__ void prep_x_kernel(const float* __restrict__ x, __half* __restrict__ xh) {
    long long i = (long long)blockIdx.x * blockDim.x + threadIdx.x;
    const long long tot = (long long)NN * HD / 2;
    if (i >= tot) return;
    float2 v = ((const float2*)x)[i];
    ((__half2*)xh)[i] = __floats2half2_rn(v.x, v.y);
}

// ============================ aggregation ===================================
// One warp per dst node; packed edges (seq 8B) + fp16 row gather, batch MLP.
__global__ void agg_kernel(const __half* __restrict__ x,
                           const int* __restrict__ rowptr,
                           const int2* __restrict__ epk,
                           const float* __restrict__ innorm,
                           float* __restrict__ agg,
                           const float* __restrict__ scale,
                           const float* __restrict__ bias) {
    int warp = (blockIdx.x * blockDim.x + threadIdx.x) >> 5;
    if (warp >= NN) return;
    int lane = threadIdx.x & 31;
    int beg = rowptr[warp], end = rowptr[warp + 1];
    const uint2* x2 = (const uint2*)x;
    float4 acc = make_float4(0.f, 0.f, 0.f, 0.f);

    if (scale) {
        float4 sc = ((const float4*)scale)[lane];
        float4 bi = ((const float4*)bias)[lane];
        int j = beg;
        for (; j + 3 < end; j += 4) {
            int2 p[4]; uint2 u[4];
            #pragma unroll
            for (int q = 0; q < 4; q++) p[q] = __ldg(&epk[j + q]);
            #pragma unroll
            for (int q = 0; q < 4; q++) u[q] = x2[(size_t)p[q].x * 32 + lane];
            #pragma unroll
            for (int q = 0; q < 4; q++) {
                float w = __int_as_float(p[q].y);
                float2 a0 = __half22float2(*(__half2*)&u[q].x);
                float2 a1 = __half22float2(*(__half2*)&u[q].y);
                float t;
                t = fmaf(a0.x, sc.x, bi.x); t = t >= 0.f ? t : SLOPE * t; acc.x += w * t;
                t = fmaf(a0.y, sc.y, bi.y); t = t >= 0.f ? t : SLOPE * t; acc.y += w * t;
                t = fmaf(a1.x, sc.z, bi.z); t = t >= 0.f ? t : SLOPE * t; acc.z += w * t;
                t = fmaf(a1.y, sc.w, bi.w); t = t >= 0.f ? t : SLOPE * t; acc.w += w * t;
            }
        }
        for (; j < end; j++) {
            int2 p = __ldg(&epk[j]);
            float w = __int_as_float(p.y);
            uint2 u = x2[(size_t)p.x * 32 + lane];
            float2 a0 = __half22float2(*(__half2*)&u.x);
            float2 a1 = __half22float2(*(__half2*)&u.y);
            float t;
            t = fmaf(a0.x, sc.x, bi.x); t = t >= 0.f ? t : SLOPE * t; acc.x += w * t;
            t = fmaf(a0.y, sc.y, bi.y); t = t >= 0.f ? t : SLOPE * t; acc.y += w * t;
            t = fmaf(a1.x, sc.z, bi.z); t = t >= 0.f ? t : SLOPE * t; acc.z += w * t;
            t = fmaf(a1.y, sc.w, bi.w); t = t >= 0.f ? t : SLOPE * t; acc.w += w * t;
        }
    } else {
        int j = beg;
        for (; j + 7 < end; j += 8) {
            int2 p[8]; uint2 u[8];
            #pragma unroll
            for (int q = 0; q < 8; q++) p[q] = __ldg(&epk[j + q]);
            #pragma unroll
            for (int q = 0; q < 8; q++) u[q] = x2[(size_t)p[q].x * 32 + lane];
            #pragma unroll
            for (int q = 0; q < 8; q++) {
                float w = __int_as_float(p[q].y);
                float2 a0 = __half22float2(*(__half2*)&u[q].x);
                float2 a1 = __half22float2(*(__half2*)&u[q].y);
                acc.x += w * a0.x; acc.y += w * a0.y;
                acc.z += w * a1.x; acc.w += w * a1.y;
            }
        }
        if (j + 3 < end) {
            int2 p[4]; uint2 u[4];
            #pragma unroll
            for (int q = 0; q < 4; q++) p[q] = __ldg(&epk[j + q]);
            #pragma unroll
            for (int q = 0; q < 4; q++) u[q] = x2[(size_t)p[q].x * 32 + lane];
            #pragma unroll
            for (int q = 0; q < 4; q++) {
                float w = __int_as_float(p[q].y);
                float2 a0 = __half22float2(*(__half2*)&u[q].x);
                float2 a1 = __half22float2(*(__half2*)&u[q].y);
                acc.x += w * a0.x; acc.y += w * a0.y;
                acc.z += w * a1.x; acc.w += w * a1.y;
            }
            j += 4;
        }
        for (; j < end; j++) {
            int2 p = __ldg(&epk[j]);
            float w = __int_as_float(p.y);
            uint2 u = x2[(size_t)p.x * 32 + lane];
            float2 a0 = __half22float2(*(__half2*)&u.x);
            float2 a1 = __half22float2(*(__half2*)&u.y);
            acc.x += w * a0.x; acc.y += w * a0.y;
            acc.z += w * a1.x; acc.w += w * a1.y;
        }
    }
    float in = innorm[warp];
    acc.x *= in; acc.y *= in; acc.z *= in; acc.w *= in;
    ((float4*)agg)[(size_t)warp * 32 + lane] = acc;
}

// ===================== weight prep: W^T hi/lo bf16 ==========================
__global__ void prep_w_kernel(const float* __restrict__ Wa, const float* __restrict__ Wb,
                              const float* __restrict__ Wc_, const float* __restrict__ Wd,
                              __nv_bfloat16* __restrict__ Wt) {
    const float* W = (blockIdx.x == 0) ? Wa : (blockIdx.x == 1) ? Wb : (blockIdx.x == 2) ? Wc_ : Wd;
    __nv_bfloat16* hi_t = Wt + (size_t)blockIdx.x * 2 * 16384;
    __nv_bfloat16* lo_t = hi_t + 16384;
    for (int idx = threadIdx.x; idx < HD * HD; idx += 256) {
        int k = idx >> 7, n = idx & 127;
        float w = W[idx];
        __nv_bfloat16 h = __float2bfloat16_rn(w);
        float r = w - __bfloat162float(h);
        hi_t[n * HD + k] = h;
        lo_t[n * HD + k] = __float2bfloat16_rn(r);
    }
}

// ================= mma.sync bf16 3-pass GEMM (128x128 tile) =================
__device__ __forceinline__ uint32_t smem_u32(const void* p) {
    uint32_t a;
    asm("{ .reg .u64 t; cvta.to.shared.u64 t, %1; cvt.u32.u64 %0, t; }" : "=r"(a) : "l"(p));
    return a;
}
#define LDSM_X4(r0, r1, r2, r3, a) \
    asm volatile("ldmatrix.sync.aligned.m8n8.x4.shared.b16 {%0,%1,%2,%3}, [%4];" \
        : "=r"(r0), "=r"(r1), "=r"(r2), "=r"(r3) : "r"(a))
#define LDSM_X2(r0, r1, a) \
    asm volatile("ldmatrix.sync.aligned.m8n8.x2.shared.b16 {%0,%1}, [%2];" \
        : "=r"(r0), "=r"(r1) : "r"(a))
#define MMA16816(c, A0, A1, A2, A3, B0, B1) \
    asm volatile("mma.sync.aligned.m16n8k16.row.col.f32.bf16.bf16.f32 " \
        "{%0,%1,%2,%3}, {%4,%5,%6,%7}, {%8,%9}, {%0,%1,%2,%3};" \
        : "+f"((c)[0]), "+f"((c)[1]), "+f"((c)[2]), "+f"((c)[3]) \
        : "r"(A0), "r"(A1), "r"(A2), "r"(A3), "r"(B0), "r"(B1))

__global__ void __launch_bounds__(256, 1)
gemm_mma_kernel(const float* __restrict__ A,
                const __nv_bfloat16* __restrict__ Wt_hi,
                const __nv_bfloat16* __restrict__ Wt_lo,
                const float* __restrict__ bvec,
                __half* __restrict__ out, int act,
                float* __restrict__ stats,
                const float* __restrict__ Wcls,
                const float* __restrict__ bcls,
                float* __restrict__ cls_out) {
    extern __shared__ char smem[];
    uint32_t sbase = smem_u32(smem);
    float* s_stats = (float*)(smem + OFF_STATS);
    int tid = threadIdx.x;
    int wid = tid >> 5;
    int lane = tid & 31;
    int block_row = blockIdx.x * 128;

    if (stats && tid < 256) s_stats[tid] = 0.f;

    // ---- load A tile -> bf16 hi/lo in smem (padded) ----
    {
        int r = tid >> 1;
        int halfc = (tid & 1) * 64;
        int grow = block_row + r;
        char* dh = smem + OFF_A_HI + (r * LDA + halfc) * 2;
        char* dl = smem + OFF_A_LO + (r * LDA + halfc) * 2;
        if (grow < NN) {
            const float4* ap = (const float4*)(A + (size_t)grow * HD + halfc);
            #pragma unroll
            for (int q = 0; q < 16; q++) {
                float4 v = ap[q];
                __nv_bfloat16 h0 = __float2bfloat16_rn(v.x);
                __nv_bfloat16 h1 = __float2bfloat16_rn(v.y);
                __nv_bfloat16 h2 = __float2bfloat16_rn(v.z);
                __nv_bfloat16 h3 = __float2bfloat16_rn(v.w);
                __nv_bfloat162 ph0 = {h0, h1}, ph1 = {h2, h3};
                __nv_bfloat162 pl0 = {__float2bfloat16_rn(v.x - __bfloat162float(h0)),
                                      __float2bfloat16_rn(v.y - __bfloat162float(h1))};
                __nv_bfloat162 pl1 = {__float2bfloat16_rn(v.z - __bfloat162float(h2)),
                                      __float2bfloat16_rn(v.w - __bfloat162float(h3))};
                ((__nv_bfloat162*)(dh + q * 8))[0] = ph0;
                ((__nv_bfloat162*)(dh + q * 8))[1] = ph1;
                ((__nv_bfloat162*)(dl + q * 8))[0] = pl0;
                ((__nv_bfloat162*)(dl + q * 8))[1] = pl1;
            }
        } else {
            #pragma unroll
            for (int q = 0; q < 16; q++) {
                ((uint2*)(dh + q * 8))[0] = make_uint2(0u, 0u);
                ((uint2*)(dl + q * 8))[0] = make_uint2(0u, 0u);
            }
        }
    }
    // ---- copy W^T hi/lo into padded smem ----
    {
        const uint32_t* wh = (const uint32_t*)Wt_hi;
        const uint32_t* wl = (const uint32_t*)Wt_lo;
        #pragma unroll
        for (int i = tid; i < 8192; i += 256) {
            int n = i >> 6, kp = i & 63;
            *(uint32_t*)(smem + OFF_W_HI + n * (LDA * 2) + kp * 4) = wh[i];
            *(uint32_t*)(smem + OFF_W_LO + n * (LDA * 2) + kp * 4) = wl[i];
        }
    }
    __syncthreads();

    // ---- mma mainloop ----
    int warp_m = wid >> 1;
    int warp_n = wid & 1;
    int sub = lane >> 3, r8 = lane & 7;
    int arow = warp_m * 32 + (sub & 1) * 8 + r8;
    int akoff = (sub >> 1) * 8;
    uint32_t aAh0 = sbase + OFF_A_HI + (arow * LDA + akoff) * 2;
    uint32_t aAh1 = aAh0 + 16 * LDA * 2;
    uint32_t aAl0 = aAh0 + (OFF_A_LO - OFF_A_HI);
    uint32_t aAl1 = aAh1 + (OFF_A_LO - OFF_A_HI);
    int bl = lane & 15;
    int brow = warp_n * 64 + (bl & 7);
    int bkoff = (bl >> 3) * 8;
    uint32_t aBh = sbase + OFF_W_HI + (brow * LDA + bkoff) * 2;
    uint32_t aBl = aBh + (OFF_W_LO - OFF_W_HI);

    float acc[2][8][4];
    #pragma unroll
    for (int m = 0; m < 2; m++)
        #pragma unroll
        for (int n = 0; n < 8; n++)
            #pragma unroll
            for (int q = 0; q < 4; q++) acc[m][n][q] = 0.f;

    #pragma unroll
    for (int ks = 0; ks < 8; ks++) {
        uint32_t ah[2][4], al[2][4];
        LDSM_X4(ah[0][0], ah[0][1], ah[0][2], ah[0][3], aAh0 + ks * 32);
        LDSM_X4(ah[1][0], ah[1][1], ah[1][2], ah[1][3], aAh1 + ks * 32);
        LDSM_X4(al[0][0], al[0][1], al[0][2], al[0][3], aAl0 + ks * 32);
        LDSM_X4(al[1][0], al[1][1], al[1][2], al[1][3], aAl1 + ks * 32);
        #pragma unroll
        for (int n = 0; n < 8; n++) {
            uint32_t bh0, bh1, bl0, bl1;
            LDSM_X2(bh0, bh1, aBh + n * (8 * LDA * 2) + ks * 32);
            LDSM_X2(bl0, bl1, aBl + n * (8 * LDA * 2) + ks * 32);
            #pragma unroll
            for (int m = 0; m < 2; m++) {
                MMA16816(acc[m][n], ah[m][0], ah[m][1], ah[m][2], ah[m][3], bh0, bh1);
                MMA16816(acc[m][n], ah[m][0], ah[m][1], ah[m][2], ah[m][3], bl0, bl1);
                MMA16816(acc[m][n], al[m][0], al[m][1], al[m][2], al[m][3], bh0, bh1);
            }
        }
    }

    int gid = lane >> 2, tig = lane & 3;

    if (Wcls) {
        // ---- fused classifier path ----
        __syncthreads();
        float* s_h = (float*)smem;
        #pragma unroll
        for (int n = 0; n < 8; n++) {
            int col = warp_n * 64 + n * 8 + tig * 2;
            float b0 = __ldg(&bvec[col]), b1 = __ldg(&bvec[col + 1]);
            #pragma unroll
            for (int m = 0; m < 2; m++) {
                int lr0 = warp_m * 32 + m * 16 + gid;
                int lr1 = lr0 + 8;
                float f0 = acc[m][n][0] + b0;
                float f1 = acc[m][n][1] + b1;
                float f2 = acc[m][n][2] + b0;
                float f3 = acc[m][n][3] + b1;
                f0 = f0 >= 0.f ? f0 : SLOPE * f0;
                f1 = f1 >= 0.f ? f1 : SLOPE * f1;
                f2 = f2 >= 0.f ? f2 : SLOPE * f2;
                f3 = f3 >= 0.f ? f3 : SLOPE * f3;
                s_h[lr0 * 136 + col] = f0; s_h[lr0 * 136 + col + 1] = f1;
                s_h[lr1 * 136 + col] = f2; s_h[lr1 * 136 + col + 1] = f3;
            }
        }
        float* s_wc = (float*)(smem + OFF_W_HI);
        for (int i = tid; i < HD * NC; i += 256) s_wc[i] = __ldg(&Wcls[i]);
        __syncthreads();
        int r = tid >> 1;
        int cb = (tid & 1) * 4;
        float a0 = __ldg(&bcls[cb]),     a1 = __ldg(&bcls[cb + 1]);
        float a2 = __ldg(&bcls[cb + 2]), a3 = __ldg(&bcls[cb + 3]);
        #pragma unroll 8
        for (int k = 0; k < HD; k++) {
            float hv = s_h[r * 136 + k];
            float4 w = *(float4*)(s_wc + k * NC + cb);
            a0 += hv * w.x; a1 += hv * w.y; a2 += hv * w.z; a3 += hv * w.w;
        }
        int grow = block_row + r;
        if (grow < NN)
            *(float4*)(cls_out + (size_t)grow * NC + cb) = make_float4(a0, a1, a2, a3);
        return;
    }

    // ---- normal epilogue: fp16 output ----
    #pragma unroll
    for (int n = 0; n < 8; n++) {
        int col = warp_n * 64 + n * 8 + tig * 2;
        float b0 = __ldg(&bvec[col]), b1 = __ldg(&bvec[col + 1]);
        float s1c0 = 0.f, s1c1 = 0.f, s2c0 = 0.f, s2c1 = 0.f;
        #pragma unroll
        for (int m = 0; m < 2; m++) {
            int r0 = block_row + warp_m * 32 + m * 16 + gid;
            int r1 = r0 + 8;
            float f0 = acc[m][n][0] + b0;
            float f1 = acc[m][n][1] + b1;
            float f2 = acc[m][n][2] + b0;
            float f3 = acc[m][n][3] + b1;
            if (act) {
                f0 = f0 >= 0.f ? f0 : SLOPE * f0;
                f1 = f1 >= 0.f ? f1 : SLOPE * f1;
                f2 = f2 >= 0.f ? f2 : SLOPE * f2;
                f3 = f3 >= 0.f ? f3 : SLOPE * f3;
            }
            if (r0 < NN) {
                *(__half2*)(out + (size_t)r0 * HD + col) = __floats2half2_rn(f0, f1);
                s1c0 += f0; s1c1 += f1; s2c0 += f0 * f0; s2c1 += f1 * f1;
            }
            if (r1 < NN) {
                *(__half2*)(out + (size_t)r1 * HD + col) = __floats2half2_rn(f2, f3);
                s1c0 += f2; s1c1 += f3; s2c0 += f2 * f2; s2c1 += f3 * f3;
            }
        }
        if (stats) {
            #pragma unroll
            for (int o = 4; o <= 16; o <<= 1) {
                s1c0 += __shfl_xor_sync(0xFFFFFFFFu, s1c0, o);
                s1c1 += __shfl_xor_sync(0xFFFFFFFFu, s1c1, o);
                s2c0 += __shfl_xor_sync(0xFFFFFFFFu, s2c0, o);
                s2c1 += __shfl_xor_sync(0xFFFFFFFFu, s2c1, o);
            }
            if (gid == 0) {
                atomicAdd(&s_stats[col], s1c0);
                atomicAdd(&s_stats[col + 1], s1c1);
                atomicAdd(&s_stats[128 + col], s2c0);
                atomicAdd(&s_stats[128 + col + 1], s2c1);
            }
        }
    }
    if (stats) {
        __syncthreads();
        if (tid < 256) atomicAdd(&stats[tid], s_stats[tid]);
    }
}

// scale/bias from BN stats
__global__ void sb_kernel(const float* __restrict__ stats,
                          const float* __restrict__ gamma,
                          const float* __restrict__ beta,
                          float* __restrict__ scale, float* __restrict__ bias) {
    int c = threadIdx.x;
    float mean = stats[c] * (1.f / NN);
    float var = stats[HD + c] * (1.f / NN) - mean * mean;
    float r = rsqrtf(var + EPS_BN) * gamma[c];
    scale[c] = r;
    bias[c] = beta[c] - mean * r;
}

// ---------------------------------------------------------------------------
extern "C" void kernel_launch(void* const* d_in, const int* in_sizes, int n_in,
                              void* d_out, int out_size) {
    const float* node_feat = (const float*)d_in[0];
    const int*   src       = (const int*)d_in[1];
    const int*   dst       = (const int*)d_in[2];
    const float* W1  = (const float*)d_in[3];
    const float* b1  = (const float*)d_in[4];
    const float* W2  = (const float*)d_in[5];
    const float* b2  = (const float*)d_in[6];
    const float* g1  = (const float*)d_in[7];
    const float* be1 = (const float*)d_in[8];
    const float* g2  = (const float*)d_in[9];
    const float* be2 = (const float*)d_in[10];
    const float* Wn1 = (const float*)d_in[11];
    const float* bn1 = (const float*)d_in[12];
    const float* Wn2 = (const float*)d_in[13];
    const float* bn2 = (const float*)d_in[14];
    const float* Wc  = (const float*)d_in[15];
    const float* bc  = (const float*)d_in[16];
    float* out = (float*)d_out;

    float *pA, *pOutN, *pInN, *pStats, *pScale, *pBias;
    __half *pXh, *pBh;
    __nv_bfloat16* pWt;
    int *pSrcC, *pDstC, *pExcl, *pBlk, *pRow, *pCur;
    int2* pEpk;
    cudaGetSymbolAddress((void**)&pA, g_A);
    cudaGetSymbolAddress((void**)&pXh, g_Xh);
    cudaGetSymbolAddress((void**)&pBh, g_Bh);
    cudaGetSymbolAddress((void**)&pOutN, g_outnorm);
    cudaGetSymbolAddress((void**)&pInN, g_innorm);
    cudaGetSymbolAddress((void**)&pStats, g_stats);
    cudaGetSymbolAddress((void**)&pWt, g_Wtb);
    cudaGetSymbolAddress((void**)&pScale, g_scale);
    cudaGetSymbolAddress((void**)&pBias, g_bias);
    cudaGetSymbolAddress((void**)&pSrcC, g_srccnt);
    cudaGetSymbolAddress((void**)&pDstC, g_dstcnt);
    cudaGetSymbolAddress((void**)&pExcl, g_excl);
    cudaGetSymbolAddress((void**)&pBlk, g_blksum);
    cudaGetSymbolAddress((void**)&pRow, g_rowptr);
    cudaGetSymbolAddress((void**)&pCur, g_cursor);
    cudaGetSymbolAddress((void**)&pEpk, g_epk);

    cudaFuncSetAttribute(gemm_mma_kernel, cudaFuncAttributeMaxDynamicSharedMemorySize, SM_TOTAL);

    const int TB = 256;
    const int gridN = (NN + TB - 1) / TB;
    const int gridE = (EE + TB - 1) / TB;
    const int gridAggW = (NN * 32 + TB - 1) / TB;
    const int gridPX = (int)(((long long)NN * HD / 2 + TB - 1) / TB);

    // ---- CSR build + norms + weight/input prep ----
    zero_cnt_kernel<<<gridN, TB>>>(pSrcC, pDstC);
    prep_w_kernel<<<4, TB>>>(W1, W2, Wn1, Wn2, pWt);
    prep_x_kernel<<<gridPX, TB>>>(node_feat, pXh);
    hist_kernel<<<gridE, TB>>>(src, dst, pSrcC, pDstC);
    norm_kernel<<<gridN, TB>>>(pSrcC, pDstC, pOutN, pInN);
    scan1_kernel<<<SCAN_GRID, SCAN_BLK>>>(pDstC, pExcl, pBlk);
    scan2_kernel<<<1, 1024>>>(pBlk);
    scan3_kernel<<<SCAN_GRID, SCAN_BLK>>>(pExcl, pBlk, pRow, pCur);
    fill_kernel<<<gridE, TB>>>(src, dst, pOutN, pCur, pEpk);

    // ---- conv1 ----
    agg_kernel<<<gridAggW, TB>>>(pXh, pRow, pEpk, pInN, pA, nullptr, nullptr);
    zero_stats_kernel<<<1, 256>>>(pStats);
    gemm_mma_kernel<<<GEMM_GRID, TB, SM_TOTAL>>>(pA, pWt + 0 * 16384, pWt + 1 * 16384, b1, pBh, 0, pStats, nullptr, nullptr, nullptr);
    sb_kernel<<<1, 128>>>(pStats, g1, be1, pScale, pBias);

    // ---- conv2 (BN1+lrelu fused into gather) ----
    agg_kernel<<<gridAggW, TB>>>(pBh, pRow, pEpk, pInN, pA, pScale, pBias);
    zero_stats_kernel<<<1, 256>>>(pStats);
    gemm_mma_kernel<<<GEMM_GRID, TB, SM_TOTAL>>>(pA, pWt + 2 * 16384, pWt + 3 * 16384, b2, pBh, 0, pStats, nullptr, nullptr, nullptr);
    sb_kernel<<<1, 128>>>(pStats, g2, be2, pScale, pBias);

    // ---- convnode1 (BN2+lrelu fused into gather; act in epilogue) ----
    agg_kernel<<<gridAggW, TB>>>(pBh, pRow, pEpk, pInN, pA, pScale, pBias);
    gemm_mma_kernel<<<GEMM_GRID, TB, SM_TOTAL>>>(pA, pWt + 4 * 16384, pWt + 5 * 16384, bn1, pBh, 1, nullptr, nullptr, nullptr, nullptr);

    // ---- convnode2 + fused classifier: writes d_out directly ----
    agg_kernel<<<gridAggW, TB>>>(pBh, pRow, pEpk, pInN, pA, nullptr, nullptr);
    gemm_mma_kernel<<<GEMM_GRID, TB, SM_TOTAL>>>(pA, pWt + 6 * 16384, pWt + 7 * 16384, bn2, nullptr, 1, nullptr, Wc, bc, out);
}

// round 10
// speedup vs baseline: 1.0782x; 1.0782x over previous
#include <cuda_runtime.h>
#include <cuda_bf16.h>
#include <cuda_fp16.h>
#include <cstdint>

#define NN 100000
#define EE 1600000
#define HD 128
#define NC 8
#define EPS_BN 1e-5f
#define SLOPE 0.01f

#define SCAN_BLK 1024
#define SCAN_GRID ((NN + SCAN_BLK - 1) / SCAN_BLK)   // 98
#define NTILES ((NN + 127) / 128)                    // 782
#define GEMM_GRID 148                                // persistent

// padded smem row stride (bf16 elems)
#define LDA 136
#define OFF_A_HI 0
#define OFF_A_LO (128 * LDA * 2)            // 34816
#define OFF_W_HI (2 * 128 * LDA * 2)        // 69632
#define OFF_W_LO (3 * 128 * LDA * 2)        // 104448
#define OFF_STATS (4 * 128 * LDA * 2)       // 139264
#define OFF_WC   (OFF_STATS + 1024)         // 140288 (classifier W, 4KB)
#define SM_TOTAL (OFF_WC + 4096)            // 144384

// ---- device scratch (allocation-free) ----
__device__ float  g_A[(size_t)NN * HD];      // agg output (fp32)
__device__ __half g_Xh[(size_t)NN * HD];     // fp16 node_feat
__device__ __half g_Bh[(size_t)NN * HD];     // fp16 activations
__device__ float g_outnorm[NN];
__device__ float g_innorm[NN];
__device__ int   g_srccnt[NN];
__device__ int   g_dstcnt[NN];
__device__ int   g_excl[NN];
__device__ int   g_blksum[SCAN_GRID];
__device__ int   g_rowptr[NN + 1];
__device__ int   g_cursor[NN];
__device__ int   g_esrc[EE];
__device__ float g_stats[2 * HD];
__device__ float g_scale[HD];
__device__ float g_bias[HD];
__device__ __nv_bfloat16 g_Wtb[8 * 16384];

// ============================ CSR build =====================================
__global__ void zero_cnt_kernel(int* a, int* b) {
    int i = blockIdx.x * blockDim.x + threadIdx.x;
    if (i < NN) { a[i] = 0; b[i] = 0; }
}
__global__ void zero_stats_kernel(float* stats) {
    int i = threadIdx.x;
    if (i < 2 * HD) stats[i] = 0.f;
}
__global__ void hist_kernel(const int* __restrict__ src, const int* __restrict__ dst,
                            int* srccnt, int* dstcnt) {
    int e = blockIdx.x * blockDim.x + threadIdx.x;
    if (e >= EE) return;
    atomicAdd(&srccnt[src[e]], 1);
    atomicAdd(&dstcnt[dst[e]], 1);
}
__global__ void norm_kernel(const int* __restrict__ srccnt, const int* __restrict__ dstcnt,
                            float* outnorm, float* innorm) {
    int i = blockIdx.x * blockDim.x + threadIdx.x;
    if (i >= NN) return;
    outnorm[i] = rsqrtf(fmaxf((float)srccnt[i], 1.f));
    innorm[i]  = rsqrtf(fmaxf((float)dstcnt[i], 1.f));
}
__global__ void scan1_kernel(const int* __restrict__ cnt, int* excl, int* blksum) {
    __shared__ int sh[SCAN_BLK];
    int i = blockIdx.x * SCAN_BLK + threadIdx.x;
    int v = (i < NN) ? cnt[i] : 0;
    sh[threadIdx.x] = v;
    __syncthreads();
    for (int off = 1; off < SCAN_BLK; off <<= 1) {
        int t = (threadIdx.x >= off) ? sh[threadIdx.x - off] : 0;
        __syncthreads();
        sh[threadIdx.x] += t;
        __syncthreads();
    }
    if (i < NN) excl[i] = sh[threadIdx.x] - v;
    if (threadIdx.x == SCAN_BLK - 1) blksum[blockIdx.x] = sh[threadIdx.x];
}
__global__ void scan2_kernel(int* blksum) {
    __shared__ int sh[1024];
    int i = threadIdx.x;
    int v = (i < SCAN_GRID) ? blksum[i] : 0;
    sh[i] = v;
    __syncthreads();
    for (int off = 1; off < 1024; off <<= 1) {
        int t = (i >= off) ? sh[i - off] : 0;
        __syncthreads();
        sh[i] += t;
        __syncthreads();
    }
    if (i < SCAN_GRID) blksum[i] = sh[i] - v;
}
__global__ void scan3_kernel(const int* __restrict__ excl, const int* __restrict__ blksum,
                             int* rowptr, int* cursor) {
    int i = blockIdx.x * SCAN_BLK + threadIdx.x;
    if (i < NN) {
        int r = excl[i] + blksum[blockIdx.x];
        rowptr[i] = r;
        cursor[i] = r;
    }
    if (i == 0) rowptr[NN] = EE;
}
__global__ void fill_kernel(const int* __restrict__ src, const int* __restrict__ dst,
                            int* cursor, int* esrc) {
    int e = blockIdx.x * blockDim.x + threadIdx.x;
    if (e >= EE) return;
    int p = atomicAdd(&cursor[dst[e]], 1);
    esrc[p] = src[e];
}

// node_feat fp32 -> fp16
__global__ void prep_x_kernel(const float* __restrict__ x, __half* __restrict__ xh) {
    long long i = (long long)blockIdx.x * blockDim.x + threadIdx.x;
    const long long tot = (long long)NN * HD / 2;
    if (i >= tot) return;
    float2 v = ((const float2*)x)[i];
    ((__half2*)xh)[i] = __floats2half2_rn(v.x, v.y);
}

// ============================ aggregation (R8-proven) =======================
__global__ void agg_kernel(const __half* __restrict__ x,
                           const int* __restrict__ rowptr,
                           const int* __restrict__ esrc,
                           const float* __restrict__ outnorm,
                           const float* __restrict__ innorm,
                           float* __restrict__ agg,
                           const float* __restrict__ scale,
                           const float* __restrict__ bias) {
    int warp = (blockIdx.x * blockDim.x + threadIdx.x) >> 5;
    if (warp >= NN) return;
    int lane = threadIdx.x & 31;
    int beg = rowptr[warp], end = rowptr[warp + 1];
    const uint2* x2 = (const uint2*)x;
    float4 acc = make_float4(0.f, 0.f, 0.f, 0.f);

    if (scale) {
        float4 sc = ((const float4*)scale)[lane];
        float4 bi = ((const float4*)bias)[lane];
        int j = beg;
        for (; j + 1 < end; j += 2) {
            int s0 = esrc[j], s1 = esrc[j + 1];
            float w0 = outnorm[s0], w1 = outnorm[s1];
            uint2 u0 = x2[(size_t)s0 * 32 + lane];
            uint2 u1 = x2[(size_t)s1 * 32 + lane];
            float2 a0 = __half22float2(*(__half2*)&u0.x);
            float2 a1 = __half22float2(*(__half2*)&u0.y);
            float2 c0 = __half22float2(*(__half2*)&u1.x);
            float2 c1 = __half22float2(*(__half2*)&u1.y);
            float t0, t1;
            t0 = fmaf(a0.x, sc.x, bi.x); t0 = t0 >= 0.f ? t0 : SLOPE * t0;
            t1 = fmaf(c0.x, sc.x, bi.x); t1 = t1 >= 0.f ? t1 : SLOPE * t1;
            acc.x += w0 * t0 + w1 * t1;
            t0 = fmaf(a0.y, sc.y, bi.y); t0 = t0 >= 0.f ? t0 : SLOPE * t0;
            t1 = fmaf(c0.y, sc.y, bi.y); t1 = t1 >= 0.f ? t1 : SLOPE * t1;
            acc.y += w0 * t0 + w1 * t1;
            t0 = fmaf(a1.x, sc.z, bi.z); t0 = t0 >= 0.f ? t0 : SLOPE * t0;
            t1 = fmaf(c1.x, sc.z, bi.z); t1 = t1 >= 0.f ? t1 : SLOPE * t1;
            acc.z += w0 * t0 + w1 * t1;
            t0 = fmaf(a1.y, sc.w, bi.w); t0 = t0 >= 0.f ? t0 : SLOPE * t0;
            t1 = fmaf(c1.y, sc.w, bi.w); t1 = t1 >= 0.f ? t1 : SLOPE * t1;
            acc.w += w0 * t0 + w1 * t1;
        }
        if (j < end) {
            int s = esrc[j];
            float w = outnorm[s];
            uint2 u = x2[(size_t)s * 32 + lane];
            float2 a0 = __half22float2(*(__half2*)&u.x);
            float2 a1 = __half22float2(*(__half2*)&u.y);
            float t;
            t = fmaf(a0.x, sc.x, bi.x); t = t >= 0.f ? t : SLOPE * t; acc.x += w * t;
            t = fmaf(a0.y, sc.y, bi.y); t = t >= 0.f ? t : SLOPE * t; acc.y += w * t;
            t = fmaf(a1.x, sc.z, bi.z); t = t >= 0.f ? t : SLOPE * t; acc.z += w * t;
            t = fmaf(a1.y, sc.w, bi.w); t = t >= 0.f ? t : SLOPE * t; acc.w += w * t;
        }
    } else {
        int j = beg;
        for (; j + 3 < end; j += 4) {
            int s0 = esrc[j], s1 = esrc[j + 1], s2 = esrc[j + 2], s3 = esrc[j + 3];
            float w0 = outnorm[s0], w1 = outnorm[s1], w2 = outnorm[s2], w3 = outnorm[s3];
            uint2 u0 = x2[(size_t)s0 * 32 + lane];
            uint2 u1 = x2[(size_t)s1 * 32 + lane];
            uint2 u2 = x2[(size_t)s2 * 32 + lane];
            uint2 u3 = x2[(size_t)s3 * 32 + lane];
            float2 a0 = __half22float2(*(__half2*)&u0.x), a1 = __half22float2(*(__half2*)&u0.y);
            float2 b0 = __half22float2(*(__half2*)&u1.x), b1 = __half22float2(*(__half2*)&u1.y);
            float2 c0 = __half22float2(*(__half2*)&u2.x), c1 = __half22float2(*(__half2*)&u2.y);
            float2 d0 = __half22float2(*(__half2*)&u3.x), d1 = __half22float2(*(__half2*)&u3.y);
            acc.x += w0 * a0.x + w1 * b0.x + w2 * c0.x + w3 * d0.x;
            acc.y += w0 * a0.y + w1 * b0.y + w2 * c0.y + w3 * d0.y;
            acc.z += w0 * a1.x + w1 * b1.x + w2 * c1.x + w3 * d1.x;
            acc.w += w0 * a1.y + w1 * b1.y + w2 * c1.y + w3 * d1.y;
        }
        for (; j < end; j++) {
            int s = esrc[j];
            float w = outnorm[s];
            uint2 u = x2[(size_t)s * 32 + lane];
            float2 a0 = __half22float2(*(__half2*)&u.x);
            float2 a1 = __half22float2(*(__half2*)&u.y);
            acc.x += w * a0.x; acc.y += w * a0.y; acc.z += w * a1.x; acc.w += w * a1.y;
        }
    }
    float in = innorm[warp];
    acc.x *= in; acc.y *= in; acc.z *= in; acc.w *= in;
    ((float4*)agg)[(size_t)warp * 32 + lane] = acc;
}

// ===================== weight prep: W^T hi/lo bf16 ==========================
__global__ void prep_w_kernel(const float* __restrict__ Wa, const float* __restrict__ Wb,
                              const float* __restrict__ Wc_, const float* __restrict__ Wd,
                              __nv_bfloat16* __restrict__ Wt) {
    const float* W = (blockIdx.x == 0) ? Wa : (blockIdx.x == 1) ? Wb : (blockIdx.x == 2) ? Wc_ : Wd;
    __nv_bfloat16* hi_t = Wt + (size_t)blockIdx.x * 2 * 16384;
    __nv_bfloat16* lo_t = hi_t + 16384;
    for (int idx = threadIdx.x; idx < HD * HD; idx += 256) {
        int k = idx >> 7, n = idx & 127;
        float w = W[idx];
        __nv_bfloat16 h = __float2bfloat16_rn(w);
        float r = w - __bfloat162float(h);
        hi_t[n * HD + k] = h;
        lo_t[n * HD + k] = __float2bfloat16_rn(r);
    }
}

// =========== persistent mma.sync bf16 3-pass GEMM (148 blocks) ==============
__device__ __forceinline__ uint32_t smem_u32(const void* p) {
    uint32_t a;
    asm("{ .reg .u64 t; cvta.to.shared.u64 t, %1; cvt.u32.u64 %0, t; }" : "=r"(a) : "l"(p));
    return a;
}
#define LDSM_X4(r0, r1, r2, r3, a) \
    asm volatile("ldmatrix.sync.aligned.m8n8.x4.shared.b16 {%0,%1,%2,%3}, [%4];" \
        : "=r"(r0), "=r"(r1), "=r"(r2), "=r"(r3) : "r"(a))
#define LDSM_X2(r0, r1, a) \
    asm volatile("ldmatrix.sync.aligned.m8n8.x2.shared.b16 {%0,%1}, [%2];" \
        : "=r"(r0), "=r"(r1) : "r"(a))
#define MMA16816(c, A0, A1, A2, A3, B0, B1) \
    asm volatile("mma.sync.aligned.m16n8k16.row.col.f32.bf16.bf16.f32 " \
        "{%0,%1,%2,%3}, {%4,%5,%6,%7}, {%8,%9}, {%0,%1,%2,%3};" \
        : "+f"((c)[0]), "+f"((c)[1]), "+f"((c)[2]), "+f"((c)[3]) \
        : "r"(A0), "r"(A1), "r"(A2), "r"(A3), "r"(B0), "r"(B1))

__global__ void __launch_bounds__(256, 1)
gemm_mma_kernel(const float* __restrict__ A,
                const __nv_bfloat16* __restrict__ Wt_hi,
                const __nv_bfloat16* __restrict__ Wt_lo,
                const float* __restrict__ bvec,
                __half* __restrict__ out, int act,
                float* __restrict__ stats,
                const float* __restrict__ Wcls,
                const float* __restrict__ bcls,
                float* __restrict__ cls_out) {
    extern __shared__ char smem[];
    uint32_t sbase = smem_u32(smem);
    float* s_stats = (float*)(smem + OFF_STATS);
    int tid = threadIdx.x;
    int wid = tid >> 5;
    int lane = tid & 31;

    // ---- one-time per block: W^T hi/lo -> smem, stats zero, classifier W ----
    {
        const uint32_t* wh = (const uint32_t*)Wt_hi;
        const uint32_t* wl = (const uint32_t*)Wt_lo;
        #pragma unroll
        for (int i = tid; i < 8192; i += 256) {
            int n = i >> 6, kp = i & 63;
            *(uint32_t*)(smem + OFF_W_HI + n * (LDA * 2) + kp * 4) = wh[i];
            *(uint32_t*)(smem + OFF_W_LO + n * (LDA * 2) + kp * 4) = wl[i];
        }
    }
    if (stats) s_stats[tid] = 0.f;
    if (Wcls) {
        float* s_wc = (float*)(smem + OFF_WC);
        for (int i = tid; i < HD * NC; i += 256) s_wc[i] = __ldg(&Wcls[i]);
    }

    // warp/lane geometry (tile-invariant)
    int warp_m = wid >> 1;
    int warp_n = wid & 1;
    int sub = lane >> 3, r8 = lane & 7;
    int arow = warp_m * 32 + (sub & 1) * 8 + r8;
    int akoff = (sub >> 1) * 8;
    uint32_t aAh0 = sbase + OFF_A_HI + (arow * LDA + akoff) * 2;
    uint32_t aAh1 = aAh0 + 16 * LDA * 2;
    uint32_t aAl0 = aAh0 + (OFF_A_LO - OFF_A_HI);
    uint32_t aAl1 = aAh1 + (OFF_A_LO - OFF_A_HI);
    int bl = lane & 15;
    int brow = warp_n * 64 + (bl & 7);
    int bkoff = (bl >> 3) * 8;
    uint32_t aBh = sbase + OFF_W_HI + (brow * LDA + bkoff) * 2;
    uint32_t aBl = aBh + (OFF_W_LO - OFF_W_HI);
    int gid = lane >> 2, tig = lane & 3;

    __syncthreads();

    for (int tile = blockIdx.x; tile < NTILES; tile += GEMM_GRID) {
        int block_row = tile * 128;

        // ---- load A tile -> bf16 hi/lo smem ----
        {
            int r = tid >> 1;
            int halfc = (tid & 1) * 64;
            int grow = block_row + r;
            char* dh = smem + OFF_A_HI + (r * LDA + halfc) * 2;
            char* dl = smem + OFF_A_LO + (r * LDA + halfc) * 2;
            if (grow < NN) {
                const float4* ap = (const float4*)(A + (size_t)grow * HD + halfc);
                #pragma unroll
                for (int q = 0; q < 16; q++) {
                    float4 v = ap[q];
                    __nv_bfloat16 h0 = __float2bfloat16_rn(v.x);
                    __nv_bfloat16 h1 = __float2bfloat16_rn(v.y);
                    __nv_bfloat16 h2 = __float2bfloat16_rn(v.z);
                    __nv_bfloat16 h3 = __float2bfloat16_rn(v.w);
                    __nv_bfloat162 ph0 = {h0, h1}, ph1 = {h2, h3};
                    __nv_bfloat162 pl0 = {__float2bfloat16_rn(v.x - __bfloat162float(h0)),
                                          __float2bfloat16_rn(v.y - __bfloat162float(h1))};
                    __nv_bfloat162 pl1 = {__float2bfloat16_rn(v.z - __bfloat162float(h2)),
                                          __float2bfloat16_rn(v.w - __bfloat162float(h3))};
                    ((__nv_bfloat162*)(dh + q * 8))[0] = ph0;
                    ((__nv_bfloat162*)(dh + q * 8))[1] = ph1;
                    ((__nv_bfloat162*)(dl + q * 8))[0] = pl0;
                    ((__nv_bfloat162*)(dl + q * 8))[1] = pl1;
                }
            } else {
                #pragma unroll
                for (int q = 0; q < 16; q++) {
                    ((uint2*)(dh + q * 8))[0] = make_uint2(0u, 0u);
                    ((uint2*)(dl + q * 8))[0] = make_uint2(0u, 0u);
                }
            }
        }
        __syncthreads();

        // ---- mma mainloop ----
        float acc[2][8][4];
        #pragma unroll
        for (int m = 0; m < 2; m++)
            #pragma unroll
            for (int n = 0; n < 8; n++)
                #pragma unroll
                for (int q = 0; q < 4; q++) acc[m][n][q] = 0.f;

        #pragma unroll
        for (int ks = 0; ks < 8; ks++) {
            uint32_t ah[2][4], al[2][4];
            LDSM_X4(ah[0][0], ah[0][1], ah[0][2], ah[0][3], aAh0 + ks * 32);
            LDSM_X4(ah[1][0], ah[1][1], ah[1][2], ah[1][3], aAh1 + ks * 32);
            LDSM_X4(al[0][0], al[0][1], al[0][2], al[0][3], aAl0 + ks * 32);
            LDSM_X4(al[1][0], al[1][1], al[1][2], al[1][3], aAl1 + ks * 32);
            #pragma unroll
            for (int n = 0; n < 8; n++) {
                uint32_t bh0, bh1, bl0, bl1;
                LDSM_X2(bh0, bh1, aBh + n * (8 * LDA * 2) + ks * 32);
                LDSM_X2(bl0, bl1, aBl + n * (8 * LDA * 2) + ks * 32);
                #pragma unroll
                for (int m = 0; m < 2; m++) {
                    MMA16816(acc[m][n], ah[m][0], ah[m][1], ah[m][2], ah[m][3], bh0, bh1);
                    MMA16816(acc[m][n], ah[m][0], ah[m][1], ah[m][2], ah[m][3], bl0, bl1);
                    MMA16816(acc[m][n], al[m][0], al[m][1], al[m][2], al[m][3], bh0, bh1);
                }
            }
        }

        if (Wcls) {
            // ---- fused classifier epilogue ----
            __syncthreads();           // all warps done reading A smem
            float* s_h = (float*)smem; // reuse A region
            #pragma unroll
            for (int n = 0; n < 8; n++) {
                int col = warp_n * 64 + n * 8 + tig * 2;
                float b0 = __ldg(&bvec[col]), b1 = __ldg(&bvec[col + 1]);
                #pragma unroll
                for (int m = 0; m < 2; m++) {
                    int lr0 = warp_m * 32 + m * 16 + gid;
                    int lr1 = lr0 + 8;
                    float f0 = acc[m][n][0] + b0;
                    float f1 = acc[m][n][1] + b1;
                    float f2 = acc[m][n][2] + b0;
                    float f3 = acc[m][n][3] + b1;
                    f0 = f0 >= 0.f ? f0 : SLOPE * f0;
                    f1 = f1 >= 0.f ? f1 : SLOPE * f1;
                    f2 = f2 >= 0.f ? f2 : SLOPE * f2;
                    f3 = f3 >= 0.f ? f3 : SLOPE * f3;
                    s_h[lr0 * 136 + col] = f0; s_h[lr0 * 136 + col + 1] = f1;
                    s_h[lr1 * 136 + col] = f2; s_h[lr1 * 136 + col + 1] = f3;
                }
            }
            __syncthreads();
            float* s_wc = (float*)(smem + OFF_WC);
            int r = tid >> 1;
            int cb = (tid & 1) * 4;
            float a0 = __ldg(&bcls[cb]),     a1 = __ldg(&bcls[cb + 1]);
            float a2 = __ldg(&bcls[cb + 2]), a3 = __ldg(&bcls[cb + 3]);
            #pragma unroll 8
            for (int k = 0; k < HD; k++) {
                float hv = s_h[r * 136 + k];
                float4 w = *(float4*)(s_wc + k * NC + cb);
                a0 += hv * w.x; a1 += hv * w.y; a2 += hv * w.z; a3 += hv * w.w;
            }
            int grow = block_row + r;
            if (grow < NN)
                *(float4*)(cls_out + (size_t)grow * NC + cb) = make_float4(a0, a1, a2, a3);
        } else {
            // ---- normal epilogue: fp16 out + shared stats ----
            #pragma unroll
            for (int n = 0; n < 8; n++) {
                int col = warp_n * 64 + n * 8 + tig * 2;
                float b0 = __ldg(&bvec[col]), b1 = __ldg(&bvec[col + 1]);
                float s1c0 = 0.f, s1c1 = 0.f, s2c0 = 0.f, s2c1 = 0.f;
                #pragma unroll
                for (int m = 0; m < 2; m++) {
                    int r0 = block_row + warp_m * 32 + m * 16 + gid;
                    int r1 = r0 + 8;
                    float f0 = acc[m][n][0] + b0;
                    float f1 = acc[m][n][1] + b1;
                    float f2 = acc[m][n][2] + b0;
                    float f3 = acc[m][n][3] + b1;
                    if (act) {
                        f0 = f0 >= 0.f ? f0 : SLOPE * f0;
                        f1 = f1 >= 0.f ? f1 : SLOPE * f1;
                        f2 = f2 >= 0.f ? f2 : SLOPE * f2;
                        f3 = f3 >= 0.f ? f3 : SLOPE * f3;
                    }
                    if (r0 < NN) {
                        *(__half2*)(out + (size_t)r0 * HD + col) = __floats2half2_rn(f0, f1);
                        s1c0 += f0; s1c1 += f1; s2c0 += f0 * f0; s2c1 += f1 * f1;
                    }
                    if (r1 < NN) {
                        *(__half2*)(out + (size_t)r1 * HD + col) = __floats2half2_rn(f2, f3);
                        s1c0 += f2; s1c1 += f3; s2c0 += f2 * f2; s2c1 += f3 * f3;
                    }
                }
                if (stats) {
                    #pragma unroll
                    for (int o = 4; o <= 16; o <<= 1) {
                        s1c0 += __shfl_xor_sync(0xFFFFFFFFu, s1c0, o);
                        s1c1 += __shfl_xor_sync(0xFFFFFFFFu, s1c1, o);
                        s2c0 += __shfl_xor_sync(0xFFFFFFFFu, s2c0, o);
                        s2c1 += __shfl_xor_sync(0xFFFFFFFFu, s2c1, o);
                    }
                    if (gid == 0) {
                        atomicAdd(&s_stats[col], s1c0);
                        atomicAdd(&s_stats[col + 1], s1c1);
                        atomicAdd(&s_stats[128 + col], s2c0);
                        atomicAdd(&s_stats[128 + col + 1], s2c1);
                    }
                }
            }
        }
        __syncthreads();   // A smem (and s_h) dead before next tile load
    }

    if (stats) atomicAdd(&stats[tid], s_stats[tid]);
}

// scale/bias from BN stats
__global__ void sb_kernel(const float* __restrict__ stats,
                          const float* __restrict__ gamma,
                          const float* __restrict__ beta,
                          float* __restrict__ scale, float* __restrict__ bias) {
    int c = threadIdx.x;
    float mean = stats[c] * (1.f / NN);
    float var = stats[HD + c] * (1.f / NN) - mean * mean;
    float r = rsqrtf(var + EPS_BN) * gamma[c];
    scale[c] = r;
    bias[c] = beta[c] - mean * r;
}

// ---------------------------------------------------------------------------
extern "C" void kernel_launch(void* const* d_in, const int* in_sizes, int n_in,
                              void* d_out, int out_size) {
    const float* node_feat = (const float*)d_in[0];
    const int*   src       = (const int*)d_in[1];
    const int*   dst       = (const int*)d_in[2];
    const float* W1  = (const float*)d_in[3];
    const float* b1  = (const float*)d_in[4];
    const float* W2  = (const float*)d_in[5];
    const float* b2  = (const float*)d_in[6];
    const float* g1  = (const float*)d_in[7];
    const float* be1 = (const float*)d_in[8];
    const float* g2  = (const float*)d_in[9];
    const float* be2 = (const float*)d_in[10];
    const float* Wn1 = (const float*)d_in[11];
    const float* bn1 = (const float*)d_in[12];
    const float* Wn2 = (const float*)d_in[13];
    const float* bn2 = (const float*)d_in[14];
    const float* Wc  = (const float*)d_in[15];
    const float* bc  = (const float*)d_in[16];
    float* out = (float*)d_out;

    float *pA, *pOutN, *pInN, *pStats, *pScale, *pBias;
    __half *pXh, *pBh;
    __nv_bfloat16* pWt;
    int *pSrcC, *pDstC, *pExcl, *pBlk, *pRow, *pCur, *pEsrc;
    cudaGetSymbolAddress((void**)&pA, g_A);
    cudaGetSymbolAddress((void**)&pXh, g_Xh);
    cudaGetSymbolAddress((void**)&pBh, g_Bh);
    cudaGetSymbolAddress((void**)&pOutN, g_outnorm);
    cudaGetSymbolAddress((void**)&pInN, g_innorm);
    cudaGetSymbolAddress((void**)&pStats, g_stats);
    cudaGetSymbolAddress((void**)&pWt, g_Wtb);
    cudaGetSymbolAddress((void**)&pScale, g_scale);
    cudaGetSymbolAddress((void**)&pBias, g_bias);
    cudaGetSymbolAddress((void**)&pSrcC, g_srccnt);
    cudaGetSymbolAddress((void**)&pDstC, g_dstcnt);
    cudaGetSymbolAddress((void**)&pExcl, g_excl);
    cudaGetSymbolAddress((void**)&pBlk, g_blksum);
    cudaGetSymbolAddress((void**)&pRow, g_rowptr);
    cudaGetSymbolAddress((void**)&pCur, g_cursor);
    cudaGetSymbolAddress((void**)&pEsrc, g_esrc);

    cudaFuncSetAttribute(gemm_mma_kernel, cudaFuncAttributeMaxDynamicSharedMemorySize, SM_TOTAL);

    const int TB = 256;
    const int gridN = (NN + TB - 1) / TB;
    const int gridE = (EE + TB - 1) / TB;
    const int gridAggW = (NN * 32 + TB - 1) / TB;
    const int gridPX = (int)(((long long)NN * HD / 2 + TB - 1) / TB);

    // ---- CSR build + norms + weight/input prep ----
    zero_cnt_kernel<<<gridN, TB>>>(pSrcC, pDstC);
    prep_w_kernel<<<4, TB>>>(W1, W2, Wn1, Wn2, pWt);
    prep_x_kernel<<<gridPX, TB>>>(node_feat, pXh);
    hist_kernel<<<gridE, TB>>>(src, dst, pSrcC, pDstC);
    norm_kernel<<<gridN, TB>>>(pSrcC, pDstC, pOutN, pInN);
    scan1_kernel<<<SCAN_GRID, SCAN_BLK>>>(pDstC, pExcl, pBlk);
    scan2_kernel<<<1, 1024>>>(pBlk);
    scan3_kernel<<<SCAN_GRID, SCAN_BLK>>>(pExcl, pBlk, pRow, pCur);
    fill_kernel<<<gridE, TB>>>(src, dst, pCur, pEsrc);

    // ---- conv1 ----
    agg_kernel<<<gridAggW, TB>>>(pXh, pRow, pEsrc, pOutN, pInN, pA, nullptr, nullptr);
    zero_stats_kernel<<<1, 256>>>(pStats);
    gemm_mma_kernel<<<GEMM_GRID, TB, SM_TOTAL>>>(pA, pWt + 0 * 16384, pWt + 1 * 16384, b1, pBh, 0, pStats, nullptr, nullptr, nullptr);
    sb_kernel<<<1, 128>>>(pStats, g1, be1, pScale, pBias);

    // ---- conv2 (BN1+lrelu fused into gather) ----
    agg_kernel<<<gridAggW, TB>>>(pBh, pRow, pEsrc, pOutN, pInN, pA, pScale, pBias);
    zero_stats_kernel<<<1, 256>>>(pStats);
    gemm_mma_kernel<<<GEMM_GRID, TB, SM_TOTAL>>>(pA, pWt + 2 * 16384, pWt + 3 * 16384, b2, pBh, 0, pStats, nullptr, nullptr, nullptr);
    sb_kernel<<<1, 128>>>(pStats, g2, be2, pScale, pBias);

    // ---- convnode1 (BN2+lrelu fused into gather; act in epilogue) ----
    agg_kernel<<<gridAggW, TB>>>(pBh, pRow, pEsrc, pOutN, pInN, pA, pScale, pBias);
    gemm_mma_kernel<<<GEMM_GRID, TB, SM_TOTAL>>>(pA, pWt + 4 * 16384, pWt + 5 * 16384, bn1, pBh, 1, nullptr, nullptr, nullptr, nullptr);

    // ---- convnode2 + fused classifier: writes d_out directly ----
    agg_kernel<<<gridAggW, TB>>>(pBh, pRow, pEsrc, pOutN, pInN, pA, nullptr, nullptr);
    gemm_mma_kernel<<<GEMM_GRID, TB, SM_TOTAL>>>(pA, pWt + 6 * 16384, pWt + 7 * 16384, bn2, nullptr, 1, nullptr, Wc, bc, out);
}